// round 8
// baseline (speedup 1.0000x reference)
#include <cuda_runtime.h>
#include <cuda_bf16.h>
#include <cstdint>
#include <cstddef>
#include <math.h>

#define DIM    1024
#define NH     16
#define HD     64
#define BATCH  4
#define SEQ    2048
#define MTOT   (BATCH*SEQ)   // 8192
#define ACTN   ((size_t)MTOT*DIM)
#define WN     ((size_t)DIM*DIM)

// ---------------------------------------------------------------------------
// Scratch (static __device__ arrays)
// ---------------------------------------------------------------------------
__device__ __nv_bfloat16 g_xh[3*ACTN];   // q,k,v act hi
__device__ __nv_bfloat16 g_xl[3*ACTN];   // q,k,v act lo
__device__ __nv_bfloat16 g_wh[4*WN];     // wq,wk,wv,wo hi, TRANSPOSED [N,K]
__device__ __nv_bfloat16 g_wl[4*WN];     // lo
__device__ __nv_bfloat16 g_qh[ACTN];     // [b,h,s,d]
__device__ __nv_bfloat16 g_ql[ACTN];
__device__ __nv_bfloat16 g_kh[ACTN];
__device__ __nv_bfloat16 g_kl[ACTN];
__device__ __nv_bfloat16 g_vh[ACTN];
__device__ __nv_bfloat16 g_vl[ACTN];
__device__ __nv_bfloat16 g_oh[ACTN];     // attn out [b,s,h*d]
__device__ __nv_bfloat16 g_ol[ACTN];

// ---------------------------------------------------------------------------
// helpers
// ---------------------------------------------------------------------------
__device__ __forceinline__ void split2(float x, float y, uint32_t& hi, uint32_t& lo) {
    __nv_bfloat162 h, l;
    h.x = __float2bfloat16(x);
    h.y = __float2bfloat16(y);
    l.x = __float2bfloat16(x - __bfloat162float(h.x));
    l.y = __float2bfloat16(y - __bfloat162float(h.y));
    hi = *reinterpret_cast<uint32_t*>(&h);
    lo = *reinterpret_cast<uint32_t*>(&l);
}
__device__ __forceinline__ uint32_t smem_u32(const void* p) {
    return (uint32_t)__cvta_generic_to_shared(p);
}
__device__ __forceinline__ void cp16s(uint32_t s, const void* g) {
    asm volatile("cp.async.cg.shared.global [%0], [%1], 16;" :: "r"(s), "l"(g));
}
__device__ __forceinline__ void cp_commit() {
    asm volatile("cp.async.commit_group;" ::: "memory");
}
template<int N>
__device__ __forceinline__ void cp_wait() {
    asm volatile("cp.async.wait_group %0;" :: "n"(N) : "memory");
}
__device__ __forceinline__ void ldsm_x4(uint32_t* r, const void* p) {
    uint32_t a = smem_u32(p);
    asm volatile("ldmatrix.sync.aligned.m8n8.x4.shared.b16 {%0,%1,%2,%3}, [%4];"
        : "=r"(r[0]), "=r"(r[1]), "=r"(r[2]), "=r"(r[3]) : "r"(a));
}
__device__ __forceinline__ void ldsm_x4_t(uint32_t* r, const void* p) {
    uint32_t a = smem_u32(p);
    asm volatile("ldmatrix.sync.aligned.m8n8.x4.trans.shared.b16 {%0,%1,%2,%3}, [%4];"
        : "=r"(r[0]), "=r"(r[1]), "=r"(r[2]), "=r"(r[3]) : "r"(a));
}
__device__ __forceinline__ void mma_bf16(float* c, const uint32_t* a, const uint32_t* b) {
    asm volatile("mma.sync.aligned.m16n8k16.row.col.f32.bf16.bf16.f32 "
        "{%0,%1,%2,%3}, {%4,%5,%6,%7}, {%8,%9}, {%0,%1,%2,%3};"
        : "+f"(c[0]), "+f"(c[1]), "+f"(c[2]), "+f"(c[3])
        : "r"(a[0]), "r"(a[1]), "r"(a[2]), "r"(a[3]), "r"(b[0]), "r"(b[1]));
}

// ---------------------------------------------------------------------------
// Fused act split: z selects q/k/v
// ---------------------------------------------------------------------------
__global__ __launch_bounds__(256)
void split3_kernel(const float* __restrict__ q, const float* __restrict__ k,
                   const float* __restrict__ v,
                   __nv_bfloat16* __restrict__ hi, __nv_bfloat16* __restrict__ lo)
{
    const int z = blockIdx.z;
    const float* x = (z == 0) ? q : (z == 1) ? k : v;
    const size_t off = (size_t)z * ACTN;
    const int n4 = (int)(ACTN/4);
    int i = blockIdx.x*blockDim.x + threadIdx.x;
    if (i >= n4) return;
    float4 v4 = ((const float4*)x)[i];
    uint32_t h0, l0, h1, l1;
    split2(v4.x, v4.y, h0, l0);
    split2(v4.z, v4.w, h1, l1);
    *reinterpret_cast<uint2*>(hi + off + (size_t)4*i) = make_uint2(h0, h1);
    *reinterpret_cast<uint2*>(lo + off + (size_t)4*i) = make_uint2(l0, l1);
}

// ---------------------------------------------------------------------------
// Fused weight transpose-split: z selects wq/wk/wv/wo. W[K,N] -> T[N,K] hi/lo.
// ---------------------------------------------------------------------------
__global__ __launch_bounds__(256)
void wsplitT4_kernel(const float* __restrict__ wq, const float* __restrict__ wk,
                     const float* __restrict__ wv, const float* __restrict__ wo,
                     __nv_bfloat16* __restrict__ Th, __nv_bfloat16* __restrict__ Tl)
{
    __shared__ float t[32][33];
    const int z = blockIdx.z;
    const float* W = (z == 0) ? wq : (z == 1) ? wk : (z == 2) ? wv : wo;
    const size_t off = (size_t)z * WN;
    const int tx = threadIdx.x & 31, ty = threadIdx.x >> 5;
    const int n0 = blockIdx.x*32, k0 = blockIdx.y*32;
    #pragma unroll
    for (int j = 0; j < 4; j++) {
        const int kl = ty + j*8;
        t[kl][tx] = W[(size_t)(k0 + kl)*DIM + n0 + tx];
    }
    __syncthreads();
    #pragma unroll
    for (int j = 0; j < 4; j++) {
        const int nl = ty + j*8;
        const float v = t[tx][nl];
        const __nv_bfloat16 h = __float2bfloat16(v);
        const __nv_bfloat16 l = __float2bfloat16(v - __bfloat162float(h));
        const size_t idx = off + (size_t)(n0 + nl)*DIM + k0 + tx;
        Th[idx] = h;
        Tl[idx] = l;
    }
}

// ---------------------------------------------------------------------------
// Compensated bf16 GEMM (mma.sync), 2-stage cp.async pipeline.
// C = Ah@Bh^T + Al@Bh^T + Ah@Bl^T. A[M,K] row-major; B[N,K] row-major.
// Both smem tiles are [128 rows x 32 k-cols], A_STR stride.
// 128x128 tile, BK=32, 256 thr (8 warps: 4m x 2n, warp tile 32x64).
// MODE 0: fp32 C[m*N+n]. MODE 1: bf16 hi/lo head-split.
// ---------------------------------------------------------------------------
#define TBK     32
#define A_STR   40
#define A_SZ    (128*A_STR)            // 5120 elems (per tile; B identical)
#define STG_SZ  (4*A_SZ)               // aH,aL,bH,bL = 20480 elems
#define GEMM_SMEM (2*STG_SZ*2)         // 81920 B

template<int MODE>
__global__ __launch_bounds__(256)
void gemm_bf16c_kernel(const __nv_bfloat16* __restrict__ Ah,
                       const __nv_bfloat16* __restrict__ Al,
                       const __nv_bfloat16* __restrict__ Bh,
                       const __nv_bfloat16* __restrict__ Bl,
                       float* __restrict__ C,
                       __nv_bfloat16* __restrict__ Ch,
                       __nv_bfloat16* __restrict__ Cl,
                       int M, int N, int K)
{
    extern __shared__ __nv_bfloat16 smem[];

    const int tid  = threadIdx.x;
    const int lane = tid & 31;
    const int wid  = tid >> 5;
    const int wm   = wid & 3;
    const int wn   = wid >> 2;
    const int bm   = blockIdx.y, bn = blockIdx.x;

    // each thread stages 2 16B chunks per tile: (row, k-quad)
    const int lin0 = tid*2;
    const int r0 = lin0 >> 2,     q0 = (lin0 & 3) * 8;
    const int r1 = r0,            q1 = ((lin0+1) & 3) * 8;  // lin0 even -> same row

    float c[2][8][4];
    #pragma unroll
    for (int mi = 0; mi < 2; mi++)
        #pragma unroll
        for (int ni = 0; ni < 8; ni++)
            #pragma unroll
            for (int j = 0; j < 4; j++) c[mi][ni][j] = 0.f;

    auto issue = [&](int st, int kt) {
        __nv_bfloat16* aH = smem + st*STG_SZ;
        __nv_bfloat16* aL = aH + A_SZ;
        __nv_bfloat16* bH = aL + A_SZ;
        __nv_bfloat16* bL = bH + A_SZ;
        const size_t ga0 = (size_t)(bm*128 + r0)*K + kt + q0;
        const size_t ga1 = (size_t)(bm*128 + r1)*K + kt + q1;
        const size_t gb0 = (size_t)(bn*128 + r0)*K + kt + q0;
        const size_t gb1 = (size_t)(bn*128 + r1)*K + kt + q1;
        cp16s(smem_u32(aH + r0*A_STR + q0), Ah + ga0);
        cp16s(smem_u32(aH + r1*A_STR + q1), Ah + ga1);
        cp16s(smem_u32(aL + r0*A_STR + q0), Al + ga0);
        cp16s(smem_u32(aL + r1*A_STR + q1), Al + ga1);
        cp16s(smem_u32(bH + r0*A_STR + q0), Bh + gb0);
        cp16s(smem_u32(bH + r1*A_STR + q1), Bh + gb1);
        cp16s(smem_u32(bL + r0*A_STR + q0), Bl + gb0);
        cp16s(smem_u32(bL + r1*A_STR + q1), Bl + gb1);
    };

    const int NT = K / TBK;   // 32
    issue(0, 0);
    cp_commit();

    for (int it = 0; it < NT; it++) {
        const int ktn = (it+1 < NT) ? (it+1)*TBK : (NT-1)*TBK;  // dummy reload on last
        issue((it+1) & 1, ktn);
        cp_commit();
        cp_wait<1>();
        __syncthreads();

        const int st = it & 1;
        __nv_bfloat16* aH = smem + st*STG_SZ;
        __nv_bfloat16* aL = aH + A_SZ;
        __nv_bfloat16* bH = aL + A_SZ;
        __nv_bfloat16* bL = bH + A_SZ;

        #pragma unroll
        for (int ks = 0; ks < 2; ks++) {
            const int k0 = ks*16;
            uint32_t ah[2][4], al[2][4], bh[8][2], bl[8][2];
            #pragma unroll
            for (int mi = 0; mi < 2; mi++) {
                const int row = wm*32 + mi*16 + (lane & 15);
                const int col = k0 + (lane >> 4)*8;
                ldsm_x4(ah[mi], aH + row*A_STR + col);
                ldsm_x4(al[mi], aL + row*A_STR + col);
            }
            // B tile is [n-row][k-col]; non-trans ldsm over n-rows yields
            // col-major B fragments. x4 blocks: 0=(n0,k0) 1=(n1,k0) 2=(n0,k8) 3=(n1,k8)
            #pragma unroll
            for (int j = 0; j < 4; j++) {
                const int nr = wn*64 + j*16 + (lane & 15);
                const int kc = k0 + (lane >> 4)*8;
                uint32_t t[4];
                ldsm_x4(t, bH + nr*A_STR + kc);
                bh[2*j][0]=t[0]; bh[2*j][1]=t[2]; bh[2*j+1][0]=t[1]; bh[2*j+1][1]=t[3];
                ldsm_x4(t, bL + nr*A_STR + kc);
                bl[2*j][0]=t[0]; bl[2*j][1]=t[2]; bl[2*j+1][0]=t[1]; bl[2*j+1][1]=t[3];
            }
            #pragma unroll
            for (int mi = 0; mi < 2; mi++)
                #pragma unroll
                for (int ni = 0; ni < 8; ni++) {
                    mma_bf16(c[mi][ni], ah[mi], bh[ni]);
                    mma_bf16(c[mi][ni], al[mi], bh[ni]);
                    mma_bf16(c[mi][ni], ah[mi], bl[ni]);
                }
        }
        __syncthreads();
    }

    #pragma unroll
    for (int mi = 0; mi < 2; mi++)
        #pragma unroll
        for (int ni = 0; ni < 8; ni++) {
            const int row0 = bm*128 + wm*32 + mi*16 + (lane >> 2);
            const int ncol = bn*128 + wn*64 + ni*8 + (lane & 3)*2;
            #pragma unroll
            for (int half = 0; half < 2; half++) {
                const int m = row0 + half*8;
                const float x = c[mi][ni][2*half], y = c[mi][ni][2*half+1];
                if (MODE == 0) {
                    *(float2*)&C[(size_t)m*N + ncol] = make_float2(x, y);
                } else {
                    const int b = m >> 11, s = m & (SEQ-1);
                    const int h = ncol >> 6, d0 = ncol & 63;
                    const size_t idx = (((size_t)b*NH + h)*SEQ + s)*HD + d0;
                    uint32_t hi, lo;
                    split2(x, y, hi, lo);
                    *reinterpret_cast<uint32_t*>(Ch + idx) = hi;
                    *reinterpret_cast<uint32_t*>(Cl + idx) = lo;
                }
            }
        }
}

// ---------------------------------------------------------------------------
// TC causal flash attention with double-buffered cp.async K/V.
// Br=Bc=64, 4 warps. smem: Q hi/lo + 2 stages x (K,V hi/lo) = 92160 B.
// ---------------------------------------------------------------------------
#define F_STR 72
#define F_T   (64*F_STR)
#define FL_SMEM ((2*F_T + 8*F_T)*2)

__global__ __launch_bounds__(128)
void flash_mma_kernel(const __nv_bfloat16* __restrict__ Qh, const __nv_bfloat16* __restrict__ Ql,
                      const __nv_bfloat16* __restrict__ Kh, const __nv_bfloat16* __restrict__ Kl,
                      const __nv_bfloat16* __restrict__ Vh, const __nv_bfloat16* __restrict__ Vl,
                      __nv_bfloat16* __restrict__ Oh, __nv_bfloat16* __restrict__ Ol)
{
    extern __shared__ __nv_bfloat16 fs[];
    __nv_bfloat16* sQh = fs;
    __nv_bfloat16* sQl = fs + F_T;

    const int qb   = blockIdx.x;
    const int bh   = blockIdx.y;
    const int tid  = threadIdx.x;
    const int lane = tid & 31;
    const int w    = tid >> 5;
    const int m0w  = w*16;

    auto issue_kv = [&](int st, int kb) {
        __nv_bfloat16* s0 = fs + 2*F_T + st*4*F_T;
        const uint32_t sb = smem_u32(s0);
        const size_t gb = ((size_t)bh*SEQ + kb*64)*HD;
        for (int i = tid; i < 512; i += 128) {
            const int row = i >> 3, cq = (i & 7)*8;
            const uint32_t off = (uint32_t)(row*F_STR + cq)*2;
            const size_t g = gb + row*64 + cq;
            cp16s(sb + off,             Kh + g);
            cp16s(sb + 2*F_T   + off,   Kl + g);
            cp16s(sb + 2*2*F_T + off,   Vh + g);
            cp16s(sb + 3*2*F_T + off,   Vl + g);
        }
    };

    issue_kv(0, 0);
    cp_commit();

    {
        const size_t gbase = ((size_t)bh*SEQ + qb*64)*HD;
        for (int i = tid; i < 512; i += 128) {
            const int row = i >> 3, cq = (i & 7)*8;
            *(uint4*)&sQh[row*F_STR + cq] = *(const uint4*)(Qh + gbase + row*64 + cq);
            *(uint4*)&sQl[row*F_STR + cq] = *(const uint4*)(Ql + gbase + row*64 + cq);
        }
    }
    __syncthreads();

    uint32_t qfh[4][4], qfl[4][4];
    #pragma unroll
    for (int ks = 0; ks < 4; ks++) {
        const int row = m0w + (lane & 15);
        const int col = ks*16 + (lane >> 4)*8;
        ldsm_x4(qfh[ks], sQh + row*F_STR + col);
        ldsm_x4(qfl[ks], sQl + row*F_STR + col);
    }

    float mr0 = -1e30f, mr1 = -1e30f, lr0 = 0.f, lr1 = 0.f;
    float o[8][4];
    #pragma unroll
    for (int j = 0; j < 8; j++)
        #pragma unroll
        for (int t = 0; t < 4; t++) o[j][t] = 0.f;

    for (int kb = 0; kb <= qb; kb++) {
        if (kb + 1 <= qb) { issue_kv((kb+1) & 1, kb+1); cp_commit(); }
        if (kb == qb) cp_wait<0>(); else cp_wait<1>();
        __syncthreads();

        __nv_bfloat16* sKh = fs + 2*F_T + (kb & 1)*4*F_T;
        __nv_bfloat16* sKl = sKh + F_T;
        __nv_bfloat16* sVh = sKh + 2*F_T;
        __nv_bfloat16* sVl = sKh + 3*F_T;

        float s[8][4];
        #pragma unroll
        for (int j = 0; j < 8; j++)
            #pragma unroll
            for (int t = 0; t < 4; t++) s[j][t] = 0.f;

        #pragma unroll
        for (int ks = 0; ks < 4; ks++) {
            uint32_t kfh[8][2], kfl[8][2];
            #pragma unroll
            for (int njp = 0; njp < 4; njp++) {
                const int row = njp*16 + ((lane & 16) ? 8 : 0) + (lane & 7);
                const int col = ks*16 + ((lane & 8) ? 8 : 0);
                uint32_t t[4];
                ldsm_x4(t, sKh + row*F_STR + col);
                kfh[2*njp][0]=t[0]; kfh[2*njp][1]=t[1]; kfh[2*njp+1][0]=t[2]; kfh[2*njp+1][1]=t[3];
                ldsm_x4(t, sKl + row*F_STR + col);
                kfl[2*njp][0]=t[0]; kfl[2*njp][1]=t[1]; kfl[2*njp+1][0]=t[2]; kfl[2*njp+1][1]=t[3];
            }
            #pragma unroll
            for (int nj = 0; nj < 8; nj++) {
                mma_bf16(s[nj], qfh[ks], kfh[nj]);
                mma_bf16(s[nj], qfl[ks], kfh[nj]);
                mma_bf16(s[nj], qfh[ks], kfl[nj]);
            }
        }

        const bool diag = (kb == qb);
        #pragma unroll
        for (int j = 0; j < 8; j++)
            #pragma unroll
            for (int t = 0; t < 4; t++) {
                s[j][t] *= 0.125f;
                if (diag) {
                    const int col = j*8 + (lane & 3)*2 + (t & 1);
                    const int row = m0w + (lane >> 2) + ((t >> 1)*8);
                    if (col > row) s[j][t] = -1e30f;
                }
            }

        float mx0 = s[0][0], mx1 = s[0][2];
        #pragma unroll
        for (int j = 0; j < 8; j++) {
            mx0 = fmaxf(mx0, fmaxf(s[j][0], s[j][1]));
            mx1 = fmaxf(mx1, fmaxf(s[j][2], s[j][3]));
        }
        #pragma unroll
        for (int off = 1; off < 4; off <<= 1) {
            mx0 = fmaxf(mx0, __shfl_xor_sync(0xffffffffu, mx0, off));
            mx1 = fmaxf(mx1, __shfl_xor_sync(0xffffffffu, mx1, off));
        }
        const float nm0 = fmaxf(mr0, mx0), nm1 = fmaxf(mr1, mx1);

        float sum0 = 0.f, sum1 = 0.f;
        #pragma unroll
        for (int j = 0; j < 8; j++) {
            s[j][0] = __expf(s[j][0] - nm0);
            s[j][1] = __expf(s[j][1] - nm0);
            s[j][2] = __expf(s[j][2] - nm1);
            s[j][3] = __expf(s[j][3] - nm1);
            sum0 += s[j][0] + s[j][1];
            sum1 += s[j][2] + s[j][3];
        }
        #pragma unroll
        for (int off = 1; off < 4; off <<= 1) {
            sum0 += __shfl_xor_sync(0xffffffffu, sum0, off);
            sum1 += __shfl_xor_sync(0xffffffffu, sum1, off);
        }
        const float a0 = __expf(mr0 - nm0), a1 = __expf(mr1 - nm1);
        lr0 = lr0*a0 + sum0;  lr1 = lr1*a1 + sum1;
        mr0 = nm0;            mr1 = nm1;
        #pragma unroll
        for (int j = 0; j < 8; j++) {
            o[j][0] *= a0; o[j][1] *= a0; o[j][2] *= a1; o[j][3] *= a1;
        }

        uint32_t aPh[4][4], aPl[4][4];
        #pragma unroll
        for (int ks = 0; ks < 4; ks++) {
            split2(s[2*ks][0],   s[2*ks][1],   aPh[ks][0], aPl[ks][0]);
            split2(s[2*ks][2],   s[2*ks][3],   aPh[ks][1], aPl[ks][1]);
            split2(s[2*ks+1][0], s[2*ks+1][1], aPh[ks][2], aPl[ks][2]);
            split2(s[2*ks+1][2], s[2*ks+1][3], aPh[ks][3], aPl[ks][3]);
        }

        #pragma unroll
        for (int ks = 0; ks < 4; ks++) {
            uint32_t vfh[8][2], vfl[8][2];
            #pragma unroll
            for (int njp = 0; njp < 4; njp++) {
                const int sel = lane >> 3, r = lane & 7;
                const int row = ks*16 + (sel & 1)*8 + r;
                const int col = njp*16 + (sel >> 1)*8;
                uint32_t t[4];
                ldsm_x4_t(t, sVh + row*F_STR + col);
                vfh[2*njp][0]=t[0]; vfh[2*njp][1]=t[1]; vfh[2*njp+1][0]=t[2]; vfh[2*njp+1][1]=t[3];
                ldsm_x4_t(t, sVl + row*F_STR + col);
                vfl[2*njp][0]=t[0]; vfl[2*njp][1]=t[1]; vfl[2*njp+1][0]=t[2]; vfl[2*njp+1][1]=t[3];
            }
            #pragma unroll
            for (int nj = 0; nj < 8; nj++) {
                mma_bf16(o[nj], aPh[ks], vfh[nj]);
                mma_bf16(o[nj], aPl[ks], vfh[nj]);
                mma_bf16(o[nj], aPh[ks], vfl[nj]);
            }
        }
        __syncthreads();   // all reads done before next iter overwrites buffer
    }

    const int b = bh >> 4, h = bh & 15;
    const float inv0 = 1.f / lr0, inv1 = 1.f / lr1;
    const int srow0 = qb*64 + m0w + (lane >> 2);
    const int srow1 = srow0 + 8;
    #pragma unroll
    for (int j = 0; j < 8; j++) {
        const int col = j*8 + (lane & 3)*2;
        uint32_t hi, lo;
        split2(o[j][0]*inv0, o[j][1]*inv0, hi, lo);
        size_t idx = ((size_t)b*SEQ + srow0)*DIM + h*HD + col;
        *reinterpret_cast<uint32_t*>(Oh + idx) = hi;
        *reinterpret_cast<uint32_t*>(Ol + idx) = lo;
        split2(o[j][2]*inv1, o[j][3]*inv1, hi, lo);
        idx = ((size_t)b*SEQ + srow1)*DIM + h*HD + col;
        *reinterpret_cast<uint32_t*>(Oh + idx) = hi;
        *reinterpret_cast<uint32_t*>(Ol + idx) = lo;
    }
}

// ---------------------------------------------------------------------------
// Launch
// ---------------------------------------------------------------------------
extern "C" void kernel_launch(void* const* d_in, const int* in_sizes, int n_in,
                              void* d_out, int out_size)
{
    const float* q  = (const float*)d_in[0];
    const float* k  = (const float*)d_in[1];
    const float* v  = (const float*)d_in[2];
    const float* wq = (const float*)d_in[3];
    const float* wk = (const float*)d_in[4];
    const float* wv = (const float*)d_in[5];
    const float* wo = (const float*)d_in[6];
    float* out = (float*)d_out;

    __nv_bfloat16 *xh, *xl, *wh, *wl, *qh, *ql, *kh, *kl, *vh, *vl, *oh, *ol;
    cudaGetSymbolAddress((void**)&xh, g_xh);
    cudaGetSymbolAddress((void**)&xl, g_xl);
    cudaGetSymbolAddress((void**)&wh, g_wh);
    cudaGetSymbolAddress((void**)&wl, g_wl);
    cudaGetSymbolAddress((void**)&qh, g_qh);
    cudaGetSymbolAddress((void**)&ql, g_ql);
    cudaGetSymbolAddress((void**)&kh, g_kh);
    cudaGetSymbolAddress((void**)&kl, g_kl);
    cudaGetSymbolAddress((void**)&vh, g_vh);
    cudaGetSymbolAddress((void**)&vl, g_vl);
    cudaGetSymbolAddress((void**)&oh, g_oh);
    cudaGetSymbolAddress((void**)&ol, g_ol);

    cudaFuncSetAttribute(gemm_bf16c_kernel<0>,
                         cudaFuncAttributeMaxDynamicSharedMemorySize, GEMM_SMEM);
    cudaFuncSetAttribute(gemm_bf16c_kernel<1>,
                         cudaFuncAttributeMaxDynamicSharedMemorySize, GEMM_SMEM);
    cudaFuncSetAttribute(flash_mma_kernel,
                         cudaFuncAttributeMaxDynamicSharedMemorySize, FL_SMEM);

    const dim3 gg(DIM/128, MTOT/128);        // (8, 64)

    split3_kernel<<<dim3((unsigned)(ACTN/4/256), 1, 3), 256>>>(q, k, v, xh, xl);
    wsplitT4_kernel<<<dim3(32, 32, 4), 256>>>(wq, wk, wv, wo, wh, wl);

    gemm_bf16c_kernel<1><<<gg, 256, GEMM_SMEM>>>(xh,        xl,        wh,      wl,      nullptr, qh, ql, MTOT, DIM, DIM);
    gemm_bf16c_kernel<1><<<gg, 256, GEMM_SMEM>>>(xh+ACTN,   xl+ACTN,   wh+WN,   wl+WN,   nullptr, kh, kl, MTOT, DIM, DIM);
    gemm_bf16c_kernel<1><<<gg, 256, GEMM_SMEM>>>(xh+2*ACTN, xl+2*ACTN, wh+2*WN, wl+2*WN, nullptr, vh, vl, MTOT, DIM, DIM);

    flash_mma_kernel<<<dim3(SEQ/64, BATCH*NH), 128, FL_SMEM>>>(
        qh, ql, kh, kl, vh, vl, oh, ol);

    gemm_bf16c_kernel<0><<<gg, 256, GEMM_SMEM>>>(oh, ol, wh+3*WN, wl+3*WN, out, nullptr, nullptr, MTOT, DIM, DIM);
}